// round 14
// baseline (speedup 1.0000x reference)
#include <cuda_runtime.h>
#include <math.h>

#define Tn 1024
#define Bn 128

// ---------------- static device scratch ----------------
// g_XP[((t*4 + g)*768 + col)*128 + b]
__device__ float g_XP[(size_t)Bn * Tn * 3072];
// g_H / g_RH: [gi*8192 + k*32 + b32], gi = g*4 + pgroup
__device__ float g_H [16 * 8192];
__device__ float g_RH[16 * 8192];
// quarter counters: [(gi*8 + which)*16], which: 0..3 rh quarters, 4..7 h quarters
__device__ unsigned g_cnt[2048];
__device__ unsigned g_headbar;

// ---------------- f32x2 helpers ----------------
static __device__ __forceinline__ unsigned long long pk2(float lo, float hi) {
    unsigned long long r;
    asm("mov.b64 %0, {%1, %2};" : "=l"(r) : "f"(lo), "f"(hi));
    return r;
}
static __device__ __forceinline__ void up2(unsigned long long v, float& lo, float& hi) {
    asm("mov.b64 {%0, %1}, %2;" : "=f"(lo), "=f"(hi) : "l"(v));
}
static __device__ __forceinline__ void fma2(unsigned long long& d,
                                            unsigned long long a,
                                            unsigned long long b) {
    asm("fma.rn.f32x2 %0, %1, %2, %0;" : "+l"(d) : "l"(a), "l"(b));
}
static __device__ __forceinline__ float sigf(float x) {
    return 1.0f / (1.0f + __expf(-x));
}
static __device__ __forceinline__ float tanhfast(float x) {
    float e = __expf(2.0f * x);
    return 1.0f - 2.0f / (e + 1.0f);
}

// ---------------- cp.async helpers ----------------
static __device__ __forceinline__ void cpa16(void* smem, const void* gmem) {
    unsigned s = (unsigned)__cvta_generic_to_shared(smem);
    asm volatile("cp.async.cg.shared.global [%0], [%1], 16;" :: "r"(s), "l"(gmem));
}
#define CPA_COMMIT() asm volatile("cp.async.commit_group;")
#define CPA_WAIT(n)  asm volatile("cp.async.wait_group %0;" :: "n"(n))

// warp-local wait: lane0 polls, warp converges (no CTA sync)
static __device__ __forceinline__ void warp_wait(volatile unsigned* c, unsigned tgt) {
    if ((threadIdx.x & 31) == 0) {
        while (*c < tgt) { __nanosleep(20); }
    }
    __syncwarp();
}

// release-publish: orders prior stores, no return value
static __device__ __forceinline__ void red_pub(unsigned* c) {
    asm volatile("red.release.gpu.global.add.u32 [%0], 1;" :: "l"(c) : "memory");
}

// ---------------- xproj SGEMM (f32x2, transposed output) + folded init ----------------
__global__ void __launch_bounds__(256) xproj_kernel(
    const float* __restrict__ X,
    const float* __restrict__ W0, const float* __restrict__ W1,
    const float* __restrict__ W2, const float* __restrict__ W3,
    const float* __restrict__ b0, const float* __restrict__ b1,
    const float* __restrict__ b2, const float* __restrict__ b3,
    const float* __restrict__ ich0, const float* __restrict__ cih0,
    float* __restrict__ out)
{
    __shared__ float As[8][128];
    __shared__ float Bs[8][128];

    const int t_  = blockIdx.y;
    const int n0  = blockIdx.x * 128;
    const int g   = n0 / 768;
    const int nc  = n0 - g * 768;
    const float* W    = (g == 0) ? W0 : (g == 1) ? W1 : (g == 2) ? W2 : W3;
    const float* bias = (g == 0) ? b0 : (g == 1) ? b1 : (g == 2) ? b2 : b3;

    const int tid  = threadIdx.x;
    const int warp = tid >> 5, lane = tid & 31;
    const int row0 = (warp & 3) * 32 + (lane >> 3) * 8;
    const int col0 = (warp >> 2) * 64 + (lane & 7) * 8;

    const int am = tid >> 1, ak = (tid & 1) * 4;
    const int bk = tid >> 5, bn = (tid & 31) * 4;

    // ---- folded init ----
    if (t_ == 0) {
        float* ci = out + 32768;
        for (int i = blockIdx.x * 256 + tid; i < Bn * 256; i += 24 * 256) {
            int b = i >> 8, d = i & 255;
            ci[((size_t)b * Tn) * 512 + d] = 0.0f;
            ci[((size_t)b * Tn + (Tn - 1)) * 512 + 256 + d] = 0.0f;
        }
        for (int i = blockIdx.x * 256 + tid; i < 2048; i += 24 * 256)
            g_cnt[i] = 0u;
        if (blockIdx.x == 0 && tid == 0) g_headbar = 0u;
        for (int i = blockIdx.x * 256 + tid; i < 16 * 8192; i += 24 * 256) {
            int gi = i >> 13;
            int gg = gi >> 2;
            int k  = (i >> 5) & 255;
            const float* h0 = (gg < 2) ? ich0 : cih0;
            g_H[i] = h0[(gg & 1) * 256 + k];
        }
    }

    unsigned long long acc[8][4];
    #pragma unroll
    for (int i = 0; i < 8; i++)
        #pragma unroll
        for (int j = 0; j < 4; j++) acc[i][j] = 0ULL;

    for (int k0 = 0; k0 < 256; k0 += 8) {
        float4 av = __ldg((const float4*)&X[(size_t)am * (Tn * 256) + t_ * 256 + k0 + ak]);
        float4 bv = __ldg((const float4*)&W[(size_t)(k0 + bk) * 768 + nc + bn]);
        __syncthreads();
        As[ak + 0][am] = av.x; As[ak + 1][am] = av.y;
        As[ak + 2][am] = av.z; As[ak + 3][am] = av.w;
        *(float4*)&Bs[bk][bn] = bv;
        __syncthreads();

        #pragma unroll
        for (int kk = 0; kk < 8; ++kk) {
            float4 a0 = *(const float4*)&As[kk][row0];
            float4 a1 = *(const float4*)&As[kk][row0 + 4];
            ulonglong2 b01 = *(const ulonglong2*)&Bs[kk][col0];
            ulonglong2 b23 = *(const ulonglong2*)&Bs[kk][col0 + 4];
            float ar[8] = {a0.x, a0.y, a0.z, a0.w, a1.x, a1.y, a1.z, a1.w};
            #pragma unroll
            for (int i = 0; i < 8; i++) {
                unsigned long long ai = pk2(ar[i], ar[i]);
                fma2(acc[i][0], ai, b01.x);
                fma2(acc[i][1], ai, b01.y);
                fma2(acc[i][2], ai, b23.x);
                fma2(acc[i][3], ai, b23.y);
            }
        }
    }

    float c[8][8];
    #pragma unroll
    for (int i = 0; i < 8; i++) {
        up2(acc[i][0], c[i][0], c[i][1]);
        up2(acc[i][1], c[i][2], c[i][3]);
        up2(acc[i][2], c[i][4], c[i][5]);
        up2(acc[i][3], c[i][6], c[i][7]);
    }
    #pragma unroll
    for (int j = 0; j < 8; j++) {
        float bb = bias[nc + col0 + j];
        size_t base = ((size_t)(t_ * 4 + g) * 768 + nc + col0 + j) * 128 + row0;
        float4 v0 = make_float4(c[0][j] + bb, c[1][j] + bb, c[2][j] + bb, c[3][j] + bb);
        float4 v1 = make_float4(c[4][j] + bb, c[5][j] + bb, c[6][j] + bb, c[7][j] + bb);
        __stcg((float4*)&g_XP[base],     v0);
        __stcg((float4*)&g_XP[base + 4], v1);
    }
}

// ---------------- scan smem layout (floats) ----------------
#define HS_OFF   0                        // 8192  : H/RH slice [256][32]
#define U1_OFF   8192                     // 16384 : zr U slab [256][64]
#define U2_OFF   (U1_OFF + 16384)         // 8192  : hh U slab [256][32]
#define XP_OFF   (U2_OFF + 8192)          // 6144  : XP double buffer [2][96][32]
#define ZS_OFF   (XP_OFF + 6144)          // 1024  : z gate [32][32]
#define HSV_OFF  (ZS_OFF + 1024)          // 1024  : saved old-H [32][32]
#define SCAN_SMEM_FLOATS (HSV_OFF + 1024)
#define SCAN_SMEM_BYTES  (SCAN_SMEM_FLOATS * 4)   // 163840 B

// ---------------- persistent scan: 128 CTAs = 4 GRU x 4 bgroup x 8 colslice ----------------
__global__ void __launch_bounds__(256, 1) scan_kernel(
    const float* __restrict__ U0, const float* __restrict__ U1,
    const float* __restrict__ U2, const float* __restrict__ U3,
    const float* __restrict__ Wm, const float* __restrict__ bm,
    const float* __restrict__ Wlv, const float* __restrict__ blv,
    float* __restrict__ out)
{
    extern __shared__ float sm[];
    float* Hs   = sm + HS_OFF;
    float* U1s  = sm + U1_OFF;
    float* U2s  = sm + U2_OFF;
    float* XPd  = sm + XP_OFF;
    float* Zs   = sm + ZS_OFF;
    float* HsSv = sm + HSV_OFF;

    const int g   = blockIdx.x >> 5;
    const int pg  = (blockIdx.x >> 3) & 3;
    const int cs  = blockIdx.x & 7;
    const int d0  = cs * 32;
    const int gi  = g * 4 + pg;
    const int tid = threadIdx.x;
    const int b   = tid & 31;
    const int jo  = tid >> 5;
    const int myq = cs >> 1;               // quarter index of this producer
    const float* U = (g == 0) ? U0 : (g == 1) ? U1 : (g == 2) ? U2 : U3;

    volatile unsigned* rhq[4];
    volatile unsigned* hq[4];
    #pragma unroll
    for (int q = 0; q < 4; q++) {
        rhq[q] = &g_cnt[(gi * 8 + q) * 16];
        hq[q]  = &g_cnt[(gi * 8 + 4 + q) * 16];
    }
    unsigned* my_rh = (unsigned*)&g_cnt[(gi * 8 + myq) * 16];
    unsigned* my_h  = (unsigned*)&g_cnt[(gi * 8 + 4 + myq) * 16];

    // resident U slabs
    for (int i = tid; i < 256 * 64; i += 256) {
        int k = i >> 6, jj = i & 63;
        int col = (jj < 32) ? (d0 + jj) : (256 + d0 + jj - 32);
        U1s[i] = U[k * 768 + col];
    }
    for (int i = tid; i < 256 * 32; i += 256) {
        int k = i >> 5, jj = i & 31;
        U2s[i] = U[k * 768 + 512 + d0 + jj];
    }

    float* myH  = g_H  + gi * 8192;
    float* myRH = g_RH + gi * 8192;
    float* ci   = out + 32768;

    const int j1 = jo * 8;
    const int j2 = jo * 4;

    // ---- prologue: stage H(0) + XP(0) ----
    #pragma unroll
    for (int ch = 0; ch < 2; ch++) {
        #pragma unroll
        for (int r = 0; r < 4; r++)
            cpa16(Hs + ch * 4096 + (r * 256 + tid) * 4,
                  myH + ch * 4096 + (r * 256 + tid) * 4);
        CPA_COMMIT();
    }
    {
        int t0 = (g & 1) ? (Tn - 1) : 0;
        const float* xpb = g_XP + ((size_t)t0 * 4 + g) * 98304;
        #pragma unroll
        for (int i = 0; i < 3; i++) {
            int idx = i * 256 + tid;
            int cl = idx >> 3, seg = idx & 7;
            int gcol = (cl < 32) ? (d0 + cl) : (cl < 64) ? (256 + d0 + cl - 32)
                                             : (512 + d0 + cl - 64);
            cpa16(XPd + cl * 32 + seg * 4, xpb + gcol * 128 + pg * 32 + seg * 4);
        }
        CPA_COMMIT();
    }
    CPA_WAIT(0);
    __syncthreads();

    for (int s = 0; s < Tn; s++) {
        const float* XPc = XPd + (s & 1) * 3072;

        // ---- prefetch XP(s+1) (group A) ----
        {
            int sn = (s < Tn - 1) ? (s + 1) : s;
            int tn_ = (g & 1) ? (Tn - 1 - sn) : sn;
            const float* xpb = g_XP + ((size_t)tn_ * 4 + g) * 98304;
            float* dst = XPd + ((s + 1) & 1) * 3072;
            #pragma unroll
            for (int i = 0; i < 3; i++) {
                int idx = i * 256 + tid;
                int cl = idx >> 3, seg = idx & 7;
                int gcol = (cl < 32) ? (d0 + cl) : (cl < 64) ? (256 + d0 + cl - 32)
                                                 : (512 + d0 + cl - 64);
                cpa16(dst + cl * 32 + seg * 4, xpb + gcol * 128 + pg * 32 + seg * 4);
            }
            CPA_COMMIT();
        }

        unsigned long long acc[4];
        #pragma unroll
        for (int p = 0; p < 4; p++)
            acc[p] = pk2(XPc[(j1 + 2 * p) * 32 + b], XPc[(j1 + 2 * p + 1) * 32 + b]);

        // ---- quarter-phased H staging (groups B0..B3) ----
        // s=0: counters at 0 pass immediately; myH holds H0 (same data as prologue)
        const unsigned htgt = (unsigned)(s * 2);
        #pragma unroll
        for (int q = 0; q < 4; q++) {
            warp_wait(hq[q], htgt);
            #pragma unroll
            for (int r = 0; r < 2; r++)
                cpa16(Hs + q * 2048 + (r * 256 + tid) * 4,
                      myH + q * 2048 + (r * 256 + tid) * 4);
            CPA_COMMIT();
        }

        // ---- phase 1: zr pre-activation, 4 k-chunks of 64 ----
        #pragma unroll
        for (int q = 0; q < 4; q++) {
            if (q == 0)      { CPA_WAIT(3); }
            else if (q == 1) { CPA_WAIT(2); }
            else if (q == 2) { CPA_WAIT(1); }
            else             { CPA_WAIT(0); }
            __syncthreads();
            const float* u1p = U1s + q * 64 * 64 + j1;
            const float* hp  = Hs + q * 64 * 32 + b;
            #pragma unroll 8
            for (int k = 0; k < 64; k++) {
                ulonglong2 ua = *(const ulonglong2*)(u1p);
                ulonglong2 ub = *(const ulonglong2*)(u1p + 4);
                float h = *hp;
                unsigned long long hd = pk2(h, h);
                fma2(acc[0], ua.x, hd); fma2(acc[1], ua.y, hd);
                fma2(acc[2], ub.x, hd); fma2(acc[3], ub.y, hd);
                u1p += 64; hp += 32;
            }
        }

        // epilogue: r-warps store rh + early publish; z-warps fill Zs
        {
            float v[8];
            #pragma unroll
            for (int p = 0; p < 4; p++) up2(acc[p], v[2 * p], v[2 * p + 1]);
            if (jo >= 4) {
                int jb = j1 - 32;
                #pragma unroll
                for (int j = 0; j < 8; j++) {
                    int d = d0 + jb + j;
                    float rh = sigf(v[j]) * Hs[d * 32 + b];
                    __stcg(myRH + d * 32 + b, rh);
                }
                asm volatile("bar.sync 1, 128;" ::: "memory");
                if (tid == 128) red_pub(my_rh);
            } else {
                #pragma unroll
                for (int j = 0; j < 8; j++)
                    Zs[(j1 + j) * 32 + b] = sigf(v[j]);
            }
            float4 hv = *(const float4*)(Hs + d0 * 32 + tid * 4);
            *(float4*)(HsSv + tid * 4) = hv;
        }
        __syncthreads();

        // ---- quarter-phased RH staging (groups C0..C3) ----
        const unsigned rtgt = (unsigned)((s + 1) * 2);
        #pragma unroll
        for (int q = 0; q < 4; q++) {
            warp_wait(rhq[q], rtgt);
            #pragma unroll
            for (int r = 0; r < 2; r++)
                cpa16(Hs + q * 2048 + (r * 256 + tid) * 4,
                      myRH + q * 2048 + (r * 256 + tid) * 4);
            CPA_COMMIT();
        }

        // ---- phase 2: candidate, 4 k-chunks of 64 ----
        unsigned long long acc2[2];
        #pragma unroll
        for (int p = 0; p < 2; p++)
            acc2[p] = pk2(XPc[(64 + j2 + 2 * p) * 32 + b],
                          XPc[(64 + j2 + 2 * p + 1) * 32 + b]);

        #pragma unroll
        for (int q = 0; q < 4; q++) {
            if (q == 0)      { CPA_WAIT(3); }
            else if (q == 1) { CPA_WAIT(2); }
            else if (q == 2) { CPA_WAIT(1); }
            else             { CPA_WAIT(0); }
            __syncthreads();
            const float* u2p = U2s + q * 64 * 32 + j2;
            const float* hp  = Hs + q * 64 * 32 + b;
            #pragma unroll 8
            for (int k = 0; k < 64; k++) {
                ulonglong2 u = *(const ulonglong2*)(u2p);
                float h = *hp;
                unsigned long long hd = pk2(h, h);
                fma2(acc2[0], u.x, hd); fma2(acc2[1], u.y, hd);
                u2p += 32; hp += 32;
            }
        }

        // epilogue: gate combine, clip, write H, publish, then ci
        float hn[4];
        {
            float w[4];
            up2(acc2[0], w[0], w[1]);
            up2(acc2[1], w[2], w[3]);
            #pragma unroll
            for (int j = 0; j < 4; j++) {
                int jl = j2 + j;
                float z  = Zs[jl * 32 + b];
                float ho = HsSv[jl * 32 + b];
                float cand = tanhfast(w[j]);
                float v = z * ho + (1.0f - z) * cand;
                hn[j] = fminf(5.0f, fmaxf(-5.0f, v));
                __stcg(myH + (d0 + jl) * 32 + b, hn[j]);
            }
        }
        __syncthreads();
        if (tid == 0) red_pub(my_h);

        // ci outputs off the fenced path
        if (g >= 2 && s < Tn - 1) {
            int Bg = pg * 32 + b;
            size_t row = (g == 2)
                ? ((size_t)Bg * Tn + s + 1) * 512 + d0 + j2
                : ((size_t)Bg * Tn + (Tn - 2 - s)) * 512 + 256 + d0 + j2;
            __stcg((float4*)(ci + row), make_float4(hn[0], hn[1], hn[2], hn[3]));
        }
    }

    // ================= fused heads (ic GRUs only) =================
    if (g < 2) {
        __syncthreads();
        if (tid == 0) {
            __threadfence();
            atomicAdd(&g_headbar, 1u);
            while (*((volatile unsigned*)&g_headbar) < 64u) { __nanosleep(64); }
            __threadfence();
        }
        __syncthreads();

        int rank = g * 32 + pg * 8 + cs;
        int b0 = rank * 2;
        float* hn0 = U1s;
        for (int i = tid; i < 2 * 512; i += 256) {
            int bb = i >> 9, kk = i & 511;
            int bat = b0 + bb;
            int pgr = bat >> 5, b32 = bat & 31;
            float v = (kk < 256) ? g_H[pgr * 8192 + kk * 32 + b32]
                                 : g_H[(4 + pgr) * 8192 + (kk - 256) * 32 + b32];
            hn0[i] = v;
        }
        __syncthreads();
        int m  = tid & 127;
        int bb = tid >> 7;
        const float* hv = hn0 + bb * 512;
        float am = bm[m], alv = blv[m];
        for (int k = 0; k < 512; k++) {
            float h = hv[k];
            am  += h * Wm [k * 128 + m];
            alv += h * Wlv[k * 128 + m];
        }
        out[(b0 + bb) * 128 + m] = am;
        out[16384 + (b0 + bb) * 128 + m] = sqrtf(expf(alv) + 1e-4f);
    }
}

// ---------------- launch ----------------
extern "C" void kernel_launch(void* const* d_in, const int* in_sizes, int n_in,
                              void* d_out, int out_size) {
    const float* data = (const float*)d_in[0];
    const float* icWf = (const float*)d_in[1];
    const float* icUf = (const float*)d_in[2];
    const float* icbf = (const float*)d_in[3];
    const float* icWb = (const float*)d_in[4];
    const float* icUb = (const float*)d_in[5];
    const float* icbb = (const float*)d_in[6];
    const float* ich0 = (const float*)d_in[7];
    const float* ciWf = (const float*)d_in[8];
    const float* ciUf = (const float*)d_in[9];
    const float* cibf = (const float*)d_in[10];
    const float* ciWb = (const float*)d_in[11];
    const float* ciUb = (const float*)d_in[12];
    const float* cibb = (const float*)d_in[13];
    const float* cih0 = (const float*)d_in[14];
    const float* Wm   = (const float*)d_in[15];
    const float* bm   = (const float*)d_in[16];
    const float* Wlv  = (const float*)d_in[17];
    const float* blv  = (const float*)d_in[18];
    float* out = (float*)d_out;

    cudaFuncSetAttribute(scan_kernel, cudaFuncAttributeMaxDynamicSharedMemorySize,
                         SCAN_SMEM_BYTES);

    dim3 grid(24, Tn);
    xproj_kernel<<<grid, 256>>>(data, icWf, icWb, ciWf, ciWb,
                                icbf, icbb, cibf, cibb,
                                ich0, cih0, out);

    scan_kernel<<<128, 256, SCAN_SMEM_BYTES>>>(icUf, icUb, ciUf, ciUb,
                                               Wm, bm, Wlv, blv, out);
}

// round 15
// speedup vs baseline: 1.0830x; 1.0830x over previous
#include <cuda_runtime.h>
#include <math.h>

#define Tn 1024
#define Bn 128

// ---------------- static device scratch ----------------
// g_XP[((t*4 + g)*768 + col)*128 + b]
__device__ float g_XP[(size_t)Bn * Tn * 3072];
// g_H / g_RH: [gi*8192 + k*32 + b32], gi = g*4 + pgroup
__device__ float g_H [16 * 8192];
__device__ float g_RH[16 * 8192];
// counters: [(gi*4 + which)*16], which: 0=rh_half0,1=rh_half1,2=h_half0,3=h_half1
__device__ unsigned g_cnt[1024];
__device__ unsigned g_headbar;

// ---------------- f32x2 helpers ----------------
static __device__ __forceinline__ unsigned long long pk2(float lo, float hi) {
    unsigned long long r;
    asm("mov.b64 %0, {%1, %2};" : "=l"(r) : "f"(lo), "f"(hi));
    return r;
}
static __device__ __forceinline__ void up2(unsigned long long v, float& lo, float& hi) {
    asm("mov.b64 {%0, %1}, %2;" : "=f"(lo), "=f"(hi) : "l"(v));
}
static __device__ __forceinline__ void fma2(unsigned long long& d,
                                            unsigned long long a,
                                            unsigned long long b) {
    asm("fma.rn.f32x2 %0, %1, %2, %0;" : "+l"(d) : "l"(a), "l"(b));
}
static __device__ __forceinline__ void add2(unsigned long long& d, unsigned long long a) {
    asm("add.rn.f32x2 %0, %0, %1;" : "+l"(d) : "l"(a));
}
static __device__ __forceinline__ float sigf(float x) {
    return 1.0f / (1.0f + __expf(-x));
}
static __device__ __forceinline__ float tanhfast(float x) {
    float e = __expf(2.0f * x);
    return 1.0f - 2.0f / (e + 1.0f);
}

// ---------------- cp.async helpers ----------------
static __device__ __forceinline__ void cpa16(void* smem, const void* gmem) {
    unsigned s = (unsigned)__cvta_generic_to_shared(smem);
    asm volatile("cp.async.cg.shared.global [%0], [%1], 16;" :: "r"(s), "l"(gmem));
}
#define CPA_COMMIT() asm volatile("cp.async.commit_group;")
#define CPA_WAIT(n)  asm volatile("cp.async.wait_group %0;" :: "n"(n))

// ---------------- xproj SGEMM (f32x2, transposed output) + folded init ----------------
__global__ void __launch_bounds__(256) xproj_kernel(
    const float* __restrict__ X,
    const float* __restrict__ W0, const float* __restrict__ W1,
    const float* __restrict__ W2, const float* __restrict__ W3,
    const float* __restrict__ b0, const float* __restrict__ b1,
    const float* __restrict__ b2, const float* __restrict__ b3,
    const float* __restrict__ ich0, const float* __restrict__ cih0,
    float* __restrict__ out)
{
    __shared__ float As[8][128];
    __shared__ float Bs[8][128];

    const int t_  = blockIdx.y;
    const int n0  = blockIdx.x * 128;
    const int g   = n0 / 768;
    const int nc  = n0 - g * 768;
    const float* W    = (g == 0) ? W0 : (g == 1) ? W1 : (g == 2) ? W2 : W3;
    const float* bias = (g == 0) ? b0 : (g == 1) ? b1 : (g == 2) ? b2 : b3;

    const int tid  = threadIdx.x;
    const int warp = tid >> 5, lane = tid & 31;
    const int row0 = (warp & 3) * 32 + (lane >> 3) * 8;
    const int col0 = (warp >> 2) * 64 + (lane & 7) * 8;

    const int am = tid >> 1, ak = (tid & 1) * 4;
    const int bk = tid >> 5, bn = (tid & 31) * 4;

    // ---- folded init ----
    if (t_ == 0) {
        float* ci = out + 32768;
        for (int i = blockIdx.x * 256 + tid; i < Bn * 256; i += 24 * 256) {
            int b = i >> 8, d = i & 255;
            ci[((size_t)b * Tn) * 512 + d] = 0.0f;
            ci[((size_t)b * Tn + (Tn - 1)) * 512 + 256 + d] = 0.0f;
        }
        for (int i = blockIdx.x * 256 + tid; i < 1024; i += 24 * 256)
            g_cnt[i] = 0u;
        if (blockIdx.x == 0 && tid == 0) g_headbar = 0u;
        for (int i = blockIdx.x * 256 + tid; i < 16 * 8192; i += 24 * 256) {
            int gi = i >> 13;
            int gg = gi >> 2;
            int k  = (i >> 5) & 255;
            const float* h0 = (gg < 2) ? ich0 : cih0;
            g_H[i] = h0[(gg & 1) * 256 + k];
        }
    }

    unsigned long long acc[8][4];
    #pragma unroll
    for (int i = 0; i < 8; i++)
        #pragma unroll
        for (int j = 0; j < 4; j++) acc[i][j] = 0ULL;

    for (int k0 = 0; k0 < 256; k0 += 8) {
        float4 av = __ldg((const float4*)&X[(size_t)am * (Tn * 256) + t_ * 256 + k0 + ak]);
        float4 bv = __ldg((const float4*)&W[(size_t)(k0 + bk) * 768 + nc + bn]);
        __syncthreads();
        As[ak + 0][am] = av.x; As[ak + 1][am] = av.y;
        As[ak + 2][am] = av.z; As[ak + 3][am] = av.w;
        *(float4*)&Bs[bk][bn] = bv;
        __syncthreads();

        #pragma unroll
        for (int kk = 0; kk < 8; ++kk) {
            float4 a0 = *(const float4*)&As[kk][row0];
            float4 a1 = *(const float4*)&As[kk][row0 + 4];
            ulonglong2 b01 = *(const ulonglong2*)&Bs[kk][col0];
            ulonglong2 b23 = *(const ulonglong2*)&Bs[kk][col0 + 4];
            float ar[8] = {a0.x, a0.y, a0.z, a0.w, a1.x, a1.y, a1.z, a1.w};
            #pragma unroll
            for (int i = 0; i < 8; i++) {
                unsigned long long ai = pk2(ar[i], ar[i]);
                fma2(acc[i][0], ai, b01.x);
                fma2(acc[i][1], ai, b01.y);
                fma2(acc[i][2], ai, b23.x);
                fma2(acc[i][3], ai, b23.y);
            }
        }
    }

    float c[8][8];
    #pragma unroll
    for (int i = 0; i < 8; i++) {
        up2(acc[i][0], c[i][0], c[i][1]);
        up2(acc[i][1], c[i][2], c[i][3]);
        up2(acc[i][2], c[i][4], c[i][5]);
        up2(acc[i][3], c[i][6], c[i][7]);
    }
    #pragma unroll
    for (int j = 0; j < 8; j++) {
        float bb = bias[nc + col0 + j];
        size_t base = ((size_t)(t_ * 4 + g) * 768 + nc + col0 + j) * 128 + row0;
        float4 v0 = make_float4(c[0][j] + bb, c[1][j] + bb, c[2][j] + bb, c[3][j] + bb);
        float4 v1 = make_float4(c[4][j] + bb, c[5][j] + bb, c[6][j] + bb, c[7][j] + bb);
        __stcg((float4*)&g_XP[base],     v0);
        __stcg((float4*)&g_XP[base + 4], v1);
    }
}

// ---------------- scan smem layout (floats) ----------------
#define HS_OFF   0                        // 8192  : H/RH slice [256][32]
#define U1_OFF   8192                     // 16384 : zr U slab [256][64]
#define U2_OFF   (U1_OFF + 16384)         // 8192  : hh U slab [256][32]
#define XP_OFF   (U2_OFF + 8192)          // 6144  : XP double buffer [2][96][32]
#define ZS_OFF   (XP_OFF + 6144)          // 1024  : z gate [32][32]
#define HSV_OFF  (ZS_OFF + 1024)          // 1024  : saved old-H [32][32]
#define RS_OFF   (HSV_OFF + 1024)         // 3072  : split-k partials (1536 u64)
#define SCAN_SMEM_FLOATS (RS_OFF + 3072)
#define SCAN_SMEM_BYTES  (SCAN_SMEM_FLOATS * 4)   // 176128 B

// ---------------- persistent scan: 128 CTAs = 4 GRU x 4 bgroup x 8 colslice ----------------
__global__ void __launch_bounds__(256, 1) scan_kernel(
    const float* __restrict__ U0, const float* __restrict__ U1,
    const float* __restrict__ U2, const float* __restrict__ U3,
    const float* __restrict__ Wm, const float* __restrict__ bm,
    const float* __restrict__ Wlv, const float* __restrict__ blv,
    float* __restrict__ out)
{
    extern __shared__ float sm[];
    float* Hs   = sm + HS_OFF;
    float* U1s  = sm + U1_OFF;
    float* U2s  = sm + U2_OFF;
    float* XPd  = sm + XP_OFF;
    float* Zs   = sm + ZS_OFF;
    float* HsSv = sm + HSV_OFF;
    unsigned long long* Rs = (unsigned long long*)(sm + RS_OFF);

    const int g   = blockIdx.x >> 5;
    const int pg  = (blockIdx.x >> 3) & 3;
    const int cs  = blockIdx.x & 7;
    const int d0  = cs * 32;
    const int gi  = g * 4 + pg;
    const int tid = threadIdx.x;
    const int b   = tid & 31;
    const int wid = tid >> 5;
    const int half = (cs < 4) ? 0 : 1;
    const int grp  = wid >> 2;              // 0: warps 0-3, 1: warps 4-7
    const float* U = (g == 0) ? U0 : (g == 1) ? U1 : (g == 2) ? U2 : U3;

    volatile unsigned* rhc[2];
    volatile unsigned* hc[2];
    rhc[0] = &g_cnt[(gi * 4 + 0) * 16];
    rhc[1] = &g_cnt[(gi * 4 + 1) * 16];
    hc[0]  = &g_cnt[(gi * 4 + 2) * 16];
    hc[1]  = &g_cnt[(gi * 4 + 3) * 16];
    unsigned* my_rh = (unsigned*)&g_cnt[(gi * 4 + half) * 16];
    unsigned* my_h  = (unsigned*)&g_cnt[(gi * 4 + 2 + half) * 16];

    // resident U slabs
    for (int i = tid; i < 256 * 64; i += 256) {
        int k = i >> 6, jj = i & 63;
        int col = (jj < 32) ? (d0 + jj) : (256 + d0 + jj - 32);
        U1s[i] = U[k * 768 + col];
    }
    for (int i = tid; i < 256 * 32; i += 256) {
        int k = i >> 5, jj = i & 31;
        U2s[i] = U[k * 768 + 512 + d0 + jj];
    }

    float* myH  = g_H  + gi * 8192;
    float* myRH = g_RH + gi * 8192;
    float* ci   = out + 32768;

    // phase1 tile: 16j x 32b, k-half split
    const int jg1 = wid & 3;          // j-group 0..3 (0,1: z; 2,3: r)
    const int kh  = grp;              // k half
    const int j10 = jg1 * 16;
    // phase2 tile: 16j x 32b, k-quarter split
    const int jg2 = wid & 1;
    const int kq  = wid >> 1;         // 0..3
    const int j20 = jg2 * 16;

    // ---- prologue: stage H(0) full + XP(0) ----
    #pragma unroll
    for (int ch = 0; ch < 2; ch++) {
        #pragma unroll
        for (int r = 0; r < 4; r++)
            cpa16(Hs + ch * 4096 + (r * 256 + tid) * 4,
                  myH + ch * 4096 + (r * 256 + tid) * 4);
        CPA_COMMIT();
    }
    {
        int t0 = (g & 1) ? (Tn - 1) : 0;
        const float* xpb = g_XP + ((size_t)t0 * 4 + g) * 98304;
        #pragma unroll
        for (int i = 0; i < 3; i++) {
            int idx = i * 256 + tid;
            int cl = idx >> 3, seg = idx & 7;
            int gcol = (cl < 32) ? (d0 + cl) : (cl < 64) ? (256 + d0 + cl - 32)
                                             : (512 + d0 + cl - 64);
            cpa16(XPd + cl * 32 + seg * 4, xpb + gcol * 128 + pg * 32 + seg * 4);
        }
        CPA_COMMIT();
    }
    CPA_WAIT(0);
    __syncthreads();

    for (int s = 0; s < Tn; s++) {
        const float* XPc = XPd + (s & 1) * 3072;

        // ---- stage own H chunk (decoupled halves), s>0 ----
        if (s > 0) {
            if ((tid & 127) == 0) {
                volatile unsigned* c = hc[grp];
                unsigned tgt = (unsigned)(s * 4);
                while (*c < tgt) { __nanosleep(20); }
            }
            if (grp == 0) { asm volatile("bar.sync 3, 128;" ::: "memory"); }
            else          { asm volatile("bar.sync 4, 128;" ::: "memory"); }
            {
                int base = grp * 4096;
                int lt = tid & 127;
                #pragma unroll
                for (int r = 0; r < 8; r++)
                    cpa16(Hs + base + (r * 128 + lt) * 4,
                          myH + base + (r * 128 + lt) * 4);
            }
            CPA_COMMIT();
        }
        // ---- XP prefetch (s+1) ----
        {
            int sn = (s < Tn - 1) ? (s + 1) : s;
            int tn_ = (g & 1) ? (Tn - 1 - sn) : sn;
            const float* xpb = g_XP + ((size_t)tn_ * 4 + g) * 98304;
            float* dst = XPd + ((s + 1) & 1) * 3072;
            #pragma unroll
            for (int i = 0; i < 3; i++) {
                int idx = i * 256 + tid;
                int cl = idx >> 3, seg = idx & 7;
                int gcol = (cl < 32) ? (d0 + cl) : (cl < 64) ? (256 + d0 + cl - 32)
                                                 : (512 + d0 + cl - 64);
                cpa16(dst + cl * 32 + seg * 4, xpb + gcol * 128 + pg * 32 + seg * 4);
            }
            CPA_COMMIT();
        }
        CPA_WAIT(1);   // own H chunk done (XP outstanding)
        if (grp == 0) { asm volatile("bar.sync 3, 128;" ::: "memory"); }
        else          { asm volatile("bar.sync 4, 128;" ::: "memory"); }

        // ---- phase 1: zr pre-activation, 16j x 128k per warp ----
        unsigned long long acc[8];
        if (kh == 0) {
            #pragma unroll
            for (int p = 0; p < 8; p++)
                acc[p] = pk2(XPc[(j10 + 2 * p) * 32 + b],
                             XPc[(j10 + 2 * p + 1) * 32 + b]);
        } else {
            #pragma unroll
            for (int p = 0; p < 8; p++) acc[p] = 0ULL;
        }
        {
            const float* u1p = U1s + (kh << 7) * 64 + j10;
            const float* hp  = Hs + (kh << 7) * 32 + b;
            #pragma unroll 4
            for (int k = 0; k < 128; k++) {
                ulonglong2 ua = *(const ulonglong2*)(u1p);
                ulonglong2 ub = *(const ulonglong2*)(u1p + 4);
                ulonglong2 uc = *(const ulonglong2*)(u1p + 8);
                ulonglong2 ud = *(const ulonglong2*)(u1p + 12);
                float h = *hp;
                unsigned long long hd = pk2(h, h);
                fma2(acc[0], ua.x, hd); fma2(acc[1], ua.y, hd);
                fma2(acc[2], ub.x, hd); fma2(acc[3], ub.y, hd);
                fma2(acc[4], uc.x, hd); fma2(acc[5], uc.y, hd);
                fma2(acc[6], ud.x, hd); fma2(acc[7], ud.y, hd);
                u1p += 64; hp += 32;
            }
        }
        __syncthreads();
        if (kh == 1) {
            unsigned long long* dst = Rs + ((jg1 << 5) + b) * 8;
            #pragma unroll
            for (int p = 0; p < 8; p++) dst[p] = acc[p];
        }
        // save old-H own rows (both chunks staged by now)
        {
            float4 hv = *(const float4*)(Hs + d0 * 32 + tid * 4);
            *(float4*)(HsSv + tid * 4) = hv;
        }
        __syncthreads();
        if (kh == 0) {
            const unsigned long long* src = Rs + ((jg1 << 5) + b) * 8;
            #pragma unroll
            for (int p = 0; p < 8; p++) add2(acc[p], src[p]);
            float v[16];
            #pragma unroll
            for (int p = 0; p < 8; p++) up2(acc[p], v[2 * p], v[2 * p + 1]);
            if (jg1 < 2) {        // z cols (local j10..j10+15)
                #pragma unroll
                for (int j = 0; j < 16; j++)
                    Zs[(j10 + j) * 32 + b] = sigf(v[j]);
            } else {              // r cols -> rh -> gmem
                int rb = (jg1 - 2) * 16;
                #pragma unroll
                for (int j = 0; j < 16; j++) {
                    int d = d0 + rb + j;
                    float rh = sigf(v[j]) * Hs[d * 32 + b];
                    __stcg(myRH + d * 32 + b, rh);
                }
            }
        }
        __syncthreads();
        if (tid == 0) {
            __threadfence();
            atomicAdd(my_rh, 1u);
        }

        // ---- stage RH chunk (decoupled halves) ----
        if ((tid & 127) == 0) {
            volatile unsigned* c = rhc[grp];
            unsigned tgt = (unsigned)((s + 1) * 4);
            while (*c < tgt) { __nanosleep(20); }
        }
        if (grp == 0) { asm volatile("bar.sync 3, 128;" ::: "memory"); }
        else          { asm volatile("bar.sync 4, 128;" ::: "memory"); }
        {
            int base = grp * 4096;
            int lt = tid & 127;
            #pragma unroll
            for (int r = 0; r < 8; r++)
                cpa16(Hs + base + (r * 128 + lt) * 4,
                      myRH + base + (r * 128 + lt) * 4);
        }
        CPA_COMMIT();
        CPA_WAIT(0);
        if (grp == 0) { asm volatile("bar.sync 3, 128;" ::: "memory"); }
        else          { asm volatile("bar.sync 4, 128;" ::: "memory"); }

        // ---- phase 2: candidate, 16j x 64k per warp ----
        unsigned long long acc2[8];
        if (kq == 0) {
            #pragma unroll
            for (int p = 0; p < 8; p++)
                acc2[p] = pk2(XPc[(64 + j20 + 2 * p) * 32 + b],
                              XPc[(64 + j20 + 2 * p + 1) * 32 + b]);
        } else {
            #pragma unroll
            for (int p = 0; p < 8; p++) acc2[p] = 0ULL;
        }
        {
            const float* u2p = U2s + (kq << 6) * 32 + j20;
            const float* hp  = Hs + (kq << 6) * 32 + b;
            #pragma unroll 4
            for (int k = 0; k < 64; k++) {
                ulonglong2 ua = *(const ulonglong2*)(u2p);
                ulonglong2 ub = *(const ulonglong2*)(u2p + 4);
                ulonglong2 uc = *(const ulonglong2*)(u2p + 8);
                ulonglong2 ud = *(const ulonglong2*)(u2p + 12);
                float h = *hp;
                unsigned long long hd = pk2(h, h);
                fma2(acc2[0], ua.x, hd); fma2(acc2[1], ua.y, hd);
                fma2(acc2[2], ub.x, hd); fma2(acc2[3], ub.y, hd);
                fma2(acc2[4], uc.x, hd); fma2(acc2[5], uc.y, hd);
                fma2(acc2[6], ud.x, hd); fma2(acc2[7], ud.y, hd);
                u2p += 32; hp += 32;
            }
        }
        __syncthreads();
        if (kq > 0) {
            unsigned long long* dst = Rs + ((((kq - 1) << 1) + jg2) * 32 + b) * 8;
            #pragma unroll
            for (int p = 0; p < 8; p++) dst[p] = acc2[p];
        }
        __syncthreads();

        float hn[16];
        if (kq == 0) {
            #pragma unroll
            for (int t = 0; t < 3; t++) {
                const unsigned long long* src = Rs + (((t << 1) + jg2) * 32 + b) * 8;
                #pragma unroll
                for (int p = 0; p < 8; p++) add2(acc2[p], src[p]);
            }
            float w[16];
            #pragma unroll
            for (int p = 0; p < 8; p++) up2(acc2[p], w[2 * p], w[2 * p + 1]);
            #pragma unroll
            for (int j = 0; j < 16; j++) {
                int jl = j20 + j;
                float z  = Zs[jl * 32 + b];
                float ho = HsSv[jl * 32 + b];
                float cand = tanhfast(w[j]);
                float v = z * ho + (1.0f - z) * cand;
                hn[j] = fminf(5.0f, fmaxf(-5.0f, v));
                __stcg(myH + (d0 + jl) * 32 + b, hn[j]);
            }
        }
        __syncthreads();
        if (tid == 0) {
            __threadfence();
            atomicAdd(my_h, 1u);
        }

        // ci outputs off the fenced path
        if (g >= 2 && s < Tn - 1 && kq == 0) {
            int Bg = pg * 32 + b;
            size_t row = (g == 2)
                ? ((size_t)Bg * Tn + s + 1) * 512 + d0 + j20
                : ((size_t)Bg * Tn + (Tn - 2 - s)) * 512 + 256 + d0 + j20;
            #pragma unroll
            for (int q = 0; q < 4; q++)
                __stcg((float4*)(ci + row + q * 4),
                       make_float4(hn[4 * q], hn[4 * q + 1],
                                   hn[4 * q + 2], hn[4 * q + 3]));
        }
    }

    // ================= fused heads (ic GRUs only) =================
    if (g < 2) {
        __syncthreads();
        if (tid == 0) {
            __threadfence();
            atomicAdd(&g_headbar, 1u);
            while (*((volatile unsigned*)&g_headbar) < 64u) { __nanosleep(64); }
            __threadfence();
        }
        __syncthreads();

        int rank = g * 32 + pg * 8 + cs;
        int b0 = rank * 2;
        float* hn0 = U1s;
        for (int i = tid; i < 2 * 512; i += 256) {
            int bb = i >> 9, kk = i & 511;
            int bat = b0 + bb;
            int pgr = bat >> 5, b32 = bat & 31;
            float v = (kk < 256) ? g_H[pgr * 8192 + kk * 32 + b32]
                                 : g_H[(4 + pgr) * 8192 + (kk - 256) * 32 + b32];
            hn0[i] = v;
        }
        __syncthreads();
        int m  = tid & 127;
        int bb = tid >> 7;
        const float* hv = hn0 + bb * 512;
        float am = bm[m], alv = blv[m];
        for (int k = 0; k < 512; k++) {
            float h = hv[k];
            am  += h * Wm [k * 128 + m];
            alv += h * Wlv[k * 128 + m];
        }
        out[(b0 + bb) * 128 + m] = am;
        out[16384 + (b0 + bb) * 128 + m] = sqrtf(expf(alv) + 1e-4f);
    }
}

// ---------------- launch ----------------
extern "C" void kernel_launch(void* const* d_in, const int* in_sizes, int n_in,
                              void* d_out, int out_size) {
    const float* data = (const float*)d_in[0];
    const float* icWf = (const float*)d_in[1];
    const float* icUf = (const float*)d_in[2];
    const float* icbf = (const float*)d_in[3];
    const float* icWb = (const float*)d_in[4];
    const float* icUb = (const float*)d_in[5];
    const float* icbb = (const float*)d_in[6];
    const float* ich0 = (const float*)d_in[7];
    const float* ciWf = (const float*)d_in[8];
    const float* ciUf = (const float*)d_in[9];
    const float* cibf = (const float*)d_in[10];
    const float* ciWb = (const float*)d_in[11];
    const float* ciUb = (const float*)d_in[12];
    const float* cibb = (const float*)d_in[13];
    const float* cih0 = (const float*)d_in[14];
    const float* Wm   = (const float*)d_in[15];
    const float* bm   = (const float*)d_in[16];
    const float* Wlv  = (const float*)d_in[17];
    const float* blv  = (const float*)d_in[18];
    float* out = (float*)d_out;

    cudaFuncSetAttribute(scan_kernel, cudaFuncAttributeMaxDynamicSharedMemorySize,
                         SCAN_SMEM_BYTES);

    dim3 grid(24, Tn);
    xproj_kernel<<<grid, 256>>>(data, icWf, icWb, ciWf, ciWb,
                                icbf, icbb, cibf, cibb,
                                ich0, cih0, out);

    scan_kernel<<<128, 256, SCAN_SMEM_BYTES>>>(icUf, icUb, ciUf, ciUb,
                                               Wm, bm, Wlv, blv, out);
}